// round 2
// baseline (speedup 1.0000x reference)
#include <cuda_runtime.h>

// Problem shape (fixed by the dataset)
#define NB 64
#define NA 24564
#define NC 85                       // 4 loc + 81 conf
#define NROWS (NB * NA)             // 1,572,096
#define NCONF_PER_ROW 81
#define NCONF ((unsigned)NROWS * NCONF_PER_ROW)   // 127,339,776 (divisible by 4)

#define CONF_THRESHOLD 0.01f
#define LOC_VAR 0.1f
#define SIZE_VAR 0.2f

// Kernel 1: box decode. One thread per (batch, anchor) row.
// predicts row stride is 85 floats (340 B) -> no 16B alignment, use scalar loads.
// dboxes rows are 16B-aligned float4 and reused across all 64 batches (L2-hot).
__global__ void __launch_bounds__(256) loc_kernel(
    const float* __restrict__ pred,
    const float4* __restrict__ dboxes,
    float4* __restrict__ out_loc)
{
    unsigned r = blockIdx.x * blockDim.x + threadIdx.x;
    if (r >= (unsigned)NROWS) return;

    unsigned anchor = r % (unsigned)NA;

    const float* p = pred + (size_t)r * NC;
    float l0 = __ldg(p + 0);
    float l1 = __ldg(p + 1);
    float l2 = __ldg(p + 2);
    float l3 = __ldg(p + 3);

    float4 db = __ldg(dboxes + anchor);   // (cx, cy, w, h)

    float cx = fmaf(l0 * LOC_VAR, db.z, db.x);
    float cy = fmaf(l1 * LOC_VAR, db.w, db.y);
    float w  = db.z * __expf(l2 * SIZE_VAR);
    float h  = db.w * __expf(l3 * SIZE_VAR);

    float4 box;
    box.x = cx - 0.5f * w;
    box.y = cy - 0.5f * h;
    box.z = cx + 0.5f * w;
    box.w = cy + 0.5f * h;
    out_loc[r] = box;
}

// Kernel 2: confidence indicator. Each thread handles 4 consecutive output
// elements (output float4-aligned); the corresponding input elements are
// consecutive except at row boundaries (skip the 4 loc floats) — handled
// per-element with a cheap div-by-81 (compiler lowers to mul-hi).
__global__ void __launch_bounds__(256) conf_kernel(
    const float* __restrict__ pred,
    float4* __restrict__ out_conf)
{
    unsigned t = blockIdx.x * blockDim.x + threadIdx.x;
    unsigned i0 = t * 4u;
    if (i0 >= NCONF) return;

    float v[4];
#pragma unroll
    for (int j = 0; j < 4; j++) {
        unsigned idx = i0 + (unsigned)j;
        unsigned row = idx / NCONF_PER_ROW;          // mul-hi magic
        unsigned k   = idx - row * NCONF_PER_ROW;
        float x = __ldg(pred + (size_t)row * NC + 4 + k);
        v[j] = (x > CONF_THRESHOLD) ? 1.0f : 0.0f;
    }
    out_conf[t] = make_float4(v[0], v[1], v[2], v[3]);
}

extern "C" void kernel_launch(void* const* d_in, const int* in_sizes, int n_in,
                              void* d_out, int out_size)
{
    const float*  pred   = (const float*)d_in[0];
    const float4* dboxes = (const float4*)d_in[1];
    float* out = (float*)d_out;

    // Output layout: [loc (NROWS*4 floats) | conf (NCONF floats)]
    float4* out_loc  = (float4*)out;
    float4* out_conf = (float4*)(out + (size_t)NROWS * 4);

    {
        int threads = 256;
        int blocks = (NROWS + threads - 1) / threads;
        loc_kernel<<<blocks, threads>>>(pred, dboxes, out_loc);
    }
    {
        int threads = 256;
        unsigned nthreads_total = NCONF / 4u;
        int blocks = (int)((nthreads_total + threads - 1) / threads);
        conf_kernel<<<blocks, threads>>>(pred, out_conf);
    }
}